// round 10
// baseline (speedup 1.0000x reference)
#include <cuda_runtime.h>

#define RSQRT2 0.70710678118654752440f

typedef unsigned long long u64;

__device__ float4 g_w4t[196 * 20];  // fc1 weights transposed: [widx][jj]

__global__ void transpose_fc1(const float* __restrict__ fc1w) {
    int i = blockIdx.x * blockDim.x + threadIdx.x;
    if (i < 196 * 20) {
        int widx = i / 20, jj = i % 20;
        const float4* w4 = reinterpret_cast<const float4*>(fc1w);
        g_w4t[i] = w4[jj * 196 + widx];
    }
}

__device__ __forceinline__ u64 pk2(float lo, float hi) {
    u64 r;
    asm("mov.b64 %0, {%1, %2};" : "=l"(r) : "f"(lo), "f"(hi));
    return r;
}
__device__ __forceinline__ void unpk2(u64 v, float& lo, float& hi) {
    asm("mov.b64 {%0, %1}, %2;" : "=f"(lo), "=f"(hi) : "l"(v));
}
__device__ __forceinline__ u64 bc2(float a) { return pk2(a, a); }
__device__ __forceinline__ u64 fma2(u64 a, u64 b, u64 c) {
    u64 d;
    asm("fma.rn.f32x2 %0, %1, %2, %3;" : "=l"(d) : "l"(a), "l"(b), "l"(c));
    return d;
}
__device__ __forceinline__ u64 mul2(u64 a, u64 b) {
    u64 d;
    asm("mul.rn.f32x2 %0, %1, %2;" : "=l"(d) : "l"(a), "l"(b));
    return d;
}
__device__ __forceinline__ u64 add2(u64 a, u64 b) {
    u64 d;
    asm("add.rn.f32x2 %0, %1, %2;" : "=l"(d) : "l"(a), "l"(b));
    return d;
}
#define SGN2 0x8000000080000000ULL
__device__ __forceinline__ u64 neg2(u64 a) { return a ^ SGN2; }
__device__ __forceinline__ u64 sub2(u64 a, u64 b) { return add2(a, neg2(b)); }

__device__ __forceinline__ u64 shflx64(u64 v, int m) {
    return __shfl_xor_sync(0xffffffffu, v, m);
}

#define RZ_G(c, s)                         \
    do {                                   \
        float _px = c * px + s * py;       \
        float _py = c * py - s * px;       \
        float _qx = c * qx + s * qy;       \
        float _qy = c * qy - s * qx;       \
        px = _px; py = _py; qx = _qx; qy = _qy; \
    } while (0)
#define RY_G(c, s)                         \
    do {                                   \
        float _px = c * px - s * qx;       \
        float _py = c * py + s * qy;       \
        float _qx = c * qx + s * px;       \
        float _qy = c * qy - s * py;       \
        px = _px; py = _py; qx = _qx; qy = _qy; \
    } while (0)

__global__ __launch_bounds__(128) void multi_encoding_kernel(
    const float* __restrict__ x, const float* __restrict__ crz_t,
    const float* __restrict__ ry_t, const float* __restrict__ fc1b,
    const float* __restrict__ fc2w, const float* __restrict__ fc2b,
    float* __restrict__ out, int B) {
    __shared__ float spix[32 * 113];   // 4-row band for 32 images, stride 113

    int tid = threadIdx.x;
    int r = tid & 3;                   // lane within quad = (bit3,bit2) of amps
    int iml = tid >> 2;                // image local 0..31
    int img_raw = blockIdx.x * 32 + iml;
    int img = img_raw < B ? img_raw : B - 1;
    int img0 = blockIdx.x * 32;

    // ---- constants ----
    float th = __ldg(crz_t);
    float cs1, sn1;
    sincosf(0.5f * th, &sn1, &cs1);
    float c2 = cs1 * cs1 - sn1 * sn1, s2 = 2.f * cs1 * sn1;
    float c4 = c2 * c2 - s2 * s2, s4 = 2.f * c2 * s2;

    float tr = __ldg(ry_t);
    float cr, sr;
    sincosf(0.5f * tr, &sr, &cr);
    float a1 = (cr + sr) * RSQRT2;
    float b1 = (cr - sr) * RSQRT2;
    float mc = cr * cr - sr * sr;      // cos(tr)
    float ms2 = 4.f * cr * sr;         // 2 sin(tr)
    float ms2h = 2.f * cr * sr;        // sin(tr) for double-counted cross terms

    // ---- per-lane CRZ phases for amps 4r..4r+3 ----
    u64 PHX0, PHY0, PHX1, PHY1;
    if (r == 0) {
        PHX0 = pk2(1.f, cs1);  PHY0 = pk2(0.f, -sn1);
        PHX1 = pk2(cs1, 1.f);  PHY1 = pk2(-sn1, 0.f);
    } else if (r == 1) {
        PHX0 = pk2(cs1, c2);   PHY0 = pk2(-sn1, -s2);
        PHX1 = pk2(1.f, cs1);  PHY1 = pk2(0.f, sn1);
    } else if (r == 2) {
        PHX0 = pk2(cs1, 1.f);  PHY0 = pk2(-sn1, 0.f);
        PHX1 = pk2(c2, cs1);   PHY1 = pk2(-s2, sn1);
    } else {
        PHX0 = pk2(1.f, cs1);  PHY0 = pk2(0.f, sn1);
        PHX1 = pk2(cs1, c4);   PHY1 = pk2(sn1, s4);
    }

    bool side0 = (r & 2) != 0;
    bool side1 = (r & 1) != 0;
    float sgn0 = side0 ? -1.f : 1.f;
    float sgn1 = side1 ? -1.f : 1.f;

    // ---- state ----
    u64 X0 = 0ULL, X1 = 0ULL, Y0 = 0ULL, Y1 = 0ULL;
    if (r == 0) X0 = pk2(1.f, 0.f);
    // carried xor2 partner state (for wire-0 apply; refreshed at measurement)
    u64 X0c = shflx64(X0, 2), Y0c = shflx64(Y0, 2);
    u64 X1c = shflx64(X1, 2), Y1c = shflx64(Y1, 2);

    float acc[5];
#pragma unroll
    for (int t = 0; t < 5; t++) acc[t] = 0.f;

    float Ab = RSQRT2, Bb = RSQRT2;
    int slot0 = 5 * r;
    int sbase = iml * 113;

    int widx = 0;
#pragma unroll 1
    for (int wi = 0; wi < 14; wi++) {
        int hdec = (wi == 13) ? 1 : 0;

        // ---- stage 4-row pixel band for all 32 images (coalesced) ----
        __syncthreads();
        {
            int row_top = 2 * wi;
#pragma unroll 1
            for (int idx = tid; idx < 32 * 112; idx += 128) {
                int il = idx >> 7;                 // idx / 128? no: need /112
                // idx = il*112 + k
                il = idx / 112;
                int k = idx - il * 112;
                int row = k / 28, col = k - row * 28;
                int grow = row_top + row;
                if (grow > 27) grow = 27;          // clamp (values masked later)
                int gimg = img0 + il;
                if (gimg >= B) gimg = B - 1;
                spix[il * 113 + k] =
                    __ldg(x + (size_t)gimg * 784 + grow * 28 + col);
            }
        }
        __syncthreads();

#pragma unroll 1
        for (int wj = 0; wj < 14; wj++) {
            bool wlast = (wj == 13);
            int sh = wlast ? 1 : 2;
            int msk = wlast ? 1 : 3;
            int lim = 16 >> (hdec + (wlast ? 1 : 0));
            int cbase = sbase + wj * 2;

            // ---- this lane's 5 gate angles from SMEM ----
            float gc[5], gs[5];
#pragma unroll
            for (int k = 0; k < 5; k++) {
                int slot = slot0 + k;
                int off = (slot >> sh) * 28 + (slot & msk);
                float v = (slot < lim) ? spix[cbase + off] : 0.f;
                __sincosf(0.5f * v, &gs[k], &gc[k]);
            }

            // ---- build this lane's wire unitary ----
            float px = Ab, py = 0.f, qx = Bb, qy = 0.f;
            RZ_G(gc[0], gs[0]);
            RY_G(gc[1], gs[1]);
            RZ_G(gc[2], gs[2]);
            RY_G(gc[3], gs[3]);
            RZ_G(gc[4], gs[4]);

            // ---- share all four wires' (p,q) within the quad ----
            float p0x = __shfl_sync(0xffffffffu, px, 0, 4);
            float p0y = __shfl_sync(0xffffffffu, py, 0, 4);
            float q0x = __shfl_sync(0xffffffffu, qx, 0, 4);
            float q0y = __shfl_sync(0xffffffffu, qy, 0, 4);
            float p1x = __shfl_sync(0xffffffffu, px, 1, 4);
            float p1y = __shfl_sync(0xffffffffu, py, 1, 4);
            float q1x = __shfl_sync(0xffffffffu, qx, 1, 4);
            float q1y = __shfl_sync(0xffffffffu, qy, 1, 4);
            float p2x = __shfl_sync(0xffffffffu, px, 2, 4);
            float p2y = __shfl_sync(0xffffffffu, py, 2, 4);
            float q2x = __shfl_sync(0xffffffffu, qx, 2, 4);
            float q2y = __shfl_sync(0xffffffffu, qy, 2, 4);
            float p3x = __shfl_sync(0xffffffffu, px, 3, 4);
            float p3y = __shfl_sync(0xffffffffu, py, 3, 4);
            float q3x = __shfl_sync(0xffffffffu, qx, 3, 4);
            float q3y = __shfl_sync(0xffffffffu, qy, 3, 4);

            // ---- wire 0 (bit3, xor2) using CARRIED partner state ----
            {
                u64 Ax = bc2(side0 ? -p0x : p0x);
                u64 Bx = bc2(-p0y);
                u64 Cx = bc2(q0x);
                u64 Dx = bc2(side0 ? q0y : -q0y);
                u64 nBx = neg2(Bx), nDx = neg2(Dx);
                u64 tX0 = fma2(Ax, X0, fma2(Bx, Y0, fma2(Cx, X0c, mul2(Dx, Y0c))));
                u64 tY0 = fma2(Ax, Y0, fma2(nBx, X0, fma2(Cx, Y0c, mul2(nDx, X0c))));
                u64 tX1 = fma2(Ax, X1, fma2(Bx, Y1, fma2(Cx, X1c, mul2(Dx, Y1c))));
                u64 tY1 = fma2(Ax, Y1, fma2(nBx, X1, fma2(Cx, Y1c, mul2(nDx, X1c))));
                X0 = tX0; Y0 = tY0; X1 = tX1; Y1 = tY1;
            }
            // ---- wire 1 (bit2, xor1) ----
            {
                u64 Ax = bc2(side1 ? -p1x : p1x);
                u64 Bx = bc2(-p1y);
                u64 Cx = bc2(q1x);
                u64 Dx = bc2(side1 ? q1y : -q1y);
                u64 nBx = neg2(Bx), nDx = neg2(Dx);
                u64 X0p = shflx64(X0, 1), Y0p = shflx64(Y0, 1);
                u64 X1p = shflx64(X1, 1), Y1p = shflx64(Y1, 1);
                u64 tX0 = fma2(Ax, X0, fma2(Bx, Y0, fma2(Cx, X0p, mul2(Dx, Y0p))));
                u64 tY0 = fma2(Ax, Y0, fma2(nBx, X0, fma2(Cx, Y0p, mul2(nDx, X0p))));
                u64 tX1 = fma2(Ax, X1, fma2(Bx, Y1, fma2(Cx, X1p, mul2(Dx, Y1p))));
                u64 tY1 = fma2(Ax, Y1, fma2(nBx, X1, fma2(Cx, Y1p, mul2(nDx, X1p))));
                X0 = tX0; Y0 = tY0; X1 = tX1; Y1 = tY1;
            }
            // ---- wire 2 (bit1, local) ----
            {
                u64 PX = bc2(p2x), PY = bc2(p2y), QX = bc2(q2x), QY = bc2(q2y);
                u64 PXn = neg2(PX), PYn = neg2(PY), QYn = neg2(QY);
                u64 tX0 = fma2(PX, X0, fma2(PYn, Y0, fma2(QX, X1, mul2(QYn, Y1))));
                u64 tY0 = fma2(PX, Y0, fma2(PY, X0, fma2(QX, Y1, mul2(QY, X1))));
                u64 tX1 = fma2(QX, X0, fma2(QY, Y0, fma2(PXn, X1, mul2(PYn, Y1))));
                u64 tY1 = fma2(QX, Y0, fma2(QYn, X0, fma2(PXn, Y1, mul2(PY, X1))));
                X0 = tX0; Y0 = tY0; X1 = tX1; Y1 = tY1;
            }
            // ---- wire 3 (bit0, intra-register) ----
            {
                u64 A1 = pk2(p3x, q3x);
                u64 A2c = pk2(-p3y, q3y);
                u64 A3 = pk2(q3x, -p3x);
                u64 A4 = pk2(-q3y, -p3y);
                u64 B2c = pk2(p3y, -q3y);
                u64 B4c = pk2(q3y, p3y);
                {
                    float xa, xb, ya, yb;
                    unpk2(X0, xa, xb);
                    unpk2(Y0, ya, yb);
                    u64 bxa = bc2(xa), bxb = bc2(xb), bya = bc2(ya), byb = bc2(yb);
                    X0 = fma2(bxa, A1, fma2(bya, A2c, fma2(bxb, A3, mul2(byb, A4))));
                    Y0 = fma2(bya, A1, fma2(bxa, B2c, fma2(byb, A3, mul2(bxb, B4c))));
                }
                {
                    float xa, xb, ya, yb;
                    unpk2(X1, xa, xb);
                    unpk2(Y1, ya, yb);
                    u64 bxa = bc2(xa), bxb = bc2(xb), bya = bc2(ya), byb = bc2(yb);
                    X1 = fma2(bxa, A1, fma2(bya, A2c, fma2(bxb, A3, mul2(byb, A4))));
                    Y1 = fma2(bya, A1, fma2(bxa, B2c, fma2(byb, A3, mul2(bxb, B4c))));
                }
            }
            // ---- CRZ diagonal ----
            {
                u64 oX = X0, oY = Y0;
                X0 = fma2(PHX0, oX, neg2(mul2(PHY0, oY)));
                Y0 = fma2(PHX0, oY, mul2(PHY0, oX));
                oX = X1; oY = Y1;
                X1 = fma2(PHX1, oX, neg2(mul2(PHY1, oY)));
                Y1 = fma2(PHX1, oY, mul2(PHY1, oX));
            }

            // ---- refresh carried xor2 partner state (serves x0p AND next wire0)
            X0c = shflx64(X0, 2); Y0c = shflx64(Y0, 2);
            X1c = shflx64(X1, 2); Y1c = shflx64(Y1, 2);

            // ---- measurement partials ----
            u64 PR0 = fma2(Y0, Y0, mul2(X0, X0));
            u64 PR1 = fma2(Y1, Y1, mul2(X1, X1));
            float lo, hi;
            u64 tsum = add2(PR0, PR1);
            unpk2(tsum, lo, hi);
            float sum_pr = lo + hi;
            float d0p = sgn0 * sum_pr;
            float d1p = sgn1 * sum_pr;
            u64 tdif = sub2(PR0, PR1);
            unpk2(tdif, lo, hi);
            float d2p = lo + hi;
            unpk2(PR0, lo, hi);
            float d3p = lo - hi;
            unpk2(PR1, lo, hi);
            d3p += lo - hi;

            u64 xw2 = fma2(Y0, Y1, mul2(X0, X1));
            unpk2(xw2, lo, hi);
            float x2p = lo + hi;
            float x0a, x0b, y0a, y0b, x1a, x1b, y1a, y1b;
            unpk2(X0, x0a, x0b);
            unpk2(Y0, y0a, y0b);
            unpk2(X1, x1a, x1b);
            unpk2(Y1, y1a, y1b);
            float x3p = x0a * x0b + y0a * y0b + x1a * x1b + y1a * y1b;

            // cross-lane terms: wire0 via carried regs (free), wire1 via xor1
            u64 cx = fma2(Y0, Y0c, mul2(X0, X0c));
            cx = fma2(Y1, Y1c, fma2(X1, X1c, cx));
            unpk2(cx, lo, hi);
            float x0p = lo + hi;
            u64 X0q = shflx64(X0, 1), Y0q = shflx64(Y0, 1);
            u64 X1q = shflx64(X1, 1), Y1q = shflx64(Y1, 1);
            cx = fma2(Y0, Y0q, mul2(X0, X0q));
            cx = fma2(Y1, Y1q, fma2(X1, X1q, cx));
            unpk2(cx, lo, hi);
            float x1p = lo + hi;

            float f0p = mc * d0p - ms2h * x0p;
            float f1p = mc * d1p - ms2h * x1p;
            float f2p = mc * d2p - ms2 * x2p;
            float f3p = mc * d3p - ms2 * x3p;

            // ---- reduce features across the quad ----
            u64 fA = pk2(f0p, f1p), fB = pk2(f2p, f3p);
            fA = add2(fA, shflx64(fA, 1));
            fA = add2(fA, shflx64(fA, 2));
            fB = add2(fB, shflx64(fB, 1));
            fB = add2(fB, shflx64(fB, 2));
            float f0, f1, f2, f3;
            unpk2(fA, f0, f1);
            unpk2(fB, f2, f3);

            // ---- fc1 accumulation from transposed weights ----
            const float4* wt = g_w4t + widx * 20 + r;
#pragma unroll
            for (int t = 0; t < 5; t++) {
                float4 wv = __ldg(&wt[4 * t]);
                acc[t] += f0 * wv.x + f1 * wv.y + f2 * wv.z + f3 * wv.w;
            }

            Ab = a1;
            Bb = b1;
            widx++;
        }
    }

    // ---- fc1 bias + leaky relu + fc2 ----
    float o0 = 0.f, o1 = 0.f;
#pragma unroll
    for (int t = 0; t < 5; t++) {
        int jj = 4 * t + r;
        float v = acc[t] + __ldg(fc1b + jj);
        v = v > 0.f ? v : 0.1f * v;
        o0 += v * __ldg(fc2w + jj);
        o1 += v * __ldg(fc2w + 20 + jj);
    }
    u64 po = pk2(o0, o1);
    po = add2(po, shflx64(po, 1));
    po = add2(po, shflx64(po, 2));
    if (r == 0 && img_raw < B) {
        float a, b;
        unpk2(po, a, b);
        reinterpret_cast<float2*>(out)[img] =
            make_float2(a + __ldg(fc2b + 0), b + __ldg(fc2b + 1));
    }
}

extern "C" void kernel_launch(void* const* d_in, const int* in_sizes, int n_in,
                              void* d_out, int out_size) {
    const float* x = (const float*)d_in[0];
    const float* crz_t = (const float*)d_in[1];
    const float* ry_t = (const float*)d_in[2];
    const float* fc1w = (const float*)d_in[3];
    const float* fc1b = (const float*)d_in[4];
    const float* fc2w = (const float*)d_in[5];
    const float* fc2b = (const float*)d_in[6];
    float* out = (float*)d_out;

    int B = in_sizes[0] / 784;
    transpose_fc1<<<(196 * 20 + 255) / 256, 256>>>(fc1w);
    int grid = (B + 31) / 32;
    multi_encoding_kernel<<<grid, 128>>>(x, crz_t, ry_t, fc1b, fc2w, fc2b, out,
                                         B);
}

// round 11
// speedup vs baseline: 1.3654x; 1.3654x over previous
#include <cuda_runtime.h>

#define RSQRT2 0.70710678118654752440f

typedef unsigned long long u64;

__device__ float4 g_w4t[196 * 20];  // fc1 weights transposed: [widx][jj]

__global__ void transpose_fc1(const float* __restrict__ fc1w) {
    int i = blockIdx.x * blockDim.x + threadIdx.x;
    if (i < 196 * 20) {
        int widx = i / 20, jj = i % 20;
        const float4* w4 = reinterpret_cast<const float4*>(fc1w);
        g_w4t[i] = w4[jj * 196 + widx];
    }
}

__device__ __forceinline__ u64 pk2(float lo, float hi) {
    u64 r;
    asm("mov.b64 %0, {%1, %2};" : "=l"(r) : "f"(lo), "f"(hi));
    return r;
}
__device__ __forceinline__ void unpk2(u64 v, float& lo, float& hi) {
    asm("mov.b64 {%0, %1}, %2;" : "=f"(lo), "=f"(hi) : "l"(v));
}
__device__ __forceinline__ u64 bc2(float a) { return pk2(a, a); }
__device__ __forceinline__ u64 fma2(u64 a, u64 b, u64 c) {
    u64 d;
    asm("fma.rn.f32x2 %0, %1, %2, %3;" : "=l"(d) : "l"(a), "l"(b), "l"(c));
    return d;
}
__device__ __forceinline__ u64 mul2(u64 a, u64 b) {
    u64 d;
    asm("mul.rn.f32x2 %0, %1, %2;" : "=l"(d) : "l"(a), "l"(b));
    return d;
}
__device__ __forceinline__ u64 add2(u64 a, u64 b) {
    u64 d;
    asm("add.rn.f32x2 %0, %1, %2;" : "=l"(d) : "l"(a), "l"(b));
    return d;
}
#define SGN2 0x8000000080000000ULL
__device__ __forceinline__ u64 neg2(u64 a) { return a ^ SGN2; }
__device__ __forceinline__ u64 sub2(u64 a, u64 b) { return add2(a, neg2(b)); }

__device__ __forceinline__ u64 shflx64(u64 v, int m) {
    return __shfl_xor_sync(0xffffffffu, v, m);
}

#define RZ_G(c, s)                         \
    do {                                   \
        float _px = c * px + s * py;       \
        float _py = c * py - s * px;       \
        float _qx = c * qx + s * qy;       \
        float _qy = c * qy - s * qx;       \
        px = _px; py = _py; qx = _qx; qy = _qy; \
    } while (0)
#define RY_G(c, s)                         \
    do {                                   \
        float _px = c * px - s * qx;       \
        float _py = c * py + s * qy;       \
        float _qx = c * qx + s * px;       \
        float _qy = c * qy - s * py;       \
        px = _px; py = _py; qx = _qx; qy = _qy; \
    } while (0)

__global__ __launch_bounds__(128) void multi_encoding_kernel(
    const float* __restrict__ x, const float* __restrict__ crz_t,
    const float* __restrict__ ry_t, const float* __restrict__ fc1b,
    const float* __restrict__ fc2w, const float* __restrict__ fc2b,
    float* __restrict__ out, int B) {
    int tid = threadIdx.x;
    int r = tid & 3;                       // lane within quad = (bit3,bit2) of amps
    int img_raw = blockIdx.x * 32 + (tid >> 2);
    int img = img_raw < B ? img_raw : B - 1;   // clamp (quad-coherent)
    const float* xi = x + (size_t)img * 784;

    // ---- constants ----
    float th = __ldg(crz_t);
    float cs1, sn1;
    sincosf(0.5f * th, &sn1, &cs1);
    float c2 = cs1 * cs1 - sn1 * sn1, s2 = 2.f * cs1 * sn1;
    float c4 = c2 * c2 - s2 * s2, s4 = 2.f * c2 * s2;

    float tr = __ldg(ry_t);
    float cr, sr;
    sincosf(0.5f * tr, &sr, &cr);
    float a1 = (cr + sr) * RSQRT2;   // base H*Ry for steps >= 1
    float b1 = (cr - sr) * RSQRT2;
    float mc = cr * cr - sr * sr;    // cos(tr)
    float ms2 = 4.f * cr * sr;       // 2 sin(tr)
    float ms2h = 2.f * cr * sr;      // sin(tr): cross-wire terms double-counted

    // ---- per-lane CRZ phases for amps 4r..4r+3 ----
    u64 PHX0, PHY0, PHX1, PHY1;
    if (r == 0) {
        PHX0 = pk2(1.f, cs1);  PHY0 = pk2(0.f, -sn1);
        PHX1 = pk2(cs1, 1.f);  PHY1 = pk2(-sn1, 0.f);
    } else if (r == 1) {
        PHX0 = pk2(cs1, c2);   PHY0 = pk2(-sn1, -s2);
        PHX1 = pk2(1.f, cs1);  PHY1 = pk2(0.f, sn1);
    } else if (r == 2) {
        PHX0 = pk2(cs1, 1.f);  PHY0 = pk2(-sn1, 0.f);
        PHX1 = pk2(c2, cs1);   PHY1 = pk2(-s2, sn1);
    } else {
        PHX0 = pk2(1.f, cs1);  PHY0 = pk2(0.f, sn1);
        PHX1 = pk2(cs1, c4);   PHY1 = pk2(sn1, s4);
    }

    bool side0 = (r & 2) != 0;   // bit3 of owned amps
    bool side1 = (r & 1) != 0;   // bit2
    float sgn0 = side0 ? -1.f : 1.f;
    float sgn1 = side1 ? -1.f : 1.f;

    // ---- state: lane owns amps 4r..4r+3 ----
    u64 X0 = 0ULL, X1 = 0ULL, Y0 = 0ULL, Y1 = 0ULL;
    if (r == 0) X0 = pk2(1.f, 0.f);
    // carried xor2 partner state (serves wire-0 apply; refreshed after CRZ)
    u64 X0c = shflx64(X0, 2), Y0c = shflx64(Y0, 2);
    u64 X1c = shflx64(X1, 2), Y1c = shflx64(Y1, 2);

    float acc[5];
#pragma unroll
    for (int t = 0; t < 5; t++) acc[t] = 0.f;

    float Ab = RSQRT2, Bb = RSQRT2;   // step-0 base is plain H
    int slot0 = 5 * r;                // this lane's first gate slot (r=3 -> 15)

    int widx = 0;
#pragma unroll 1
    for (int wi = 0; wi < 14; wi++) {
        int hdec = (wi == 13) ? 1 : 0;
#pragma unroll 1
        for (int wj = 0; wj < 14; wj++) {
            bool wlast = (wj == 13);
            int sh = wlast ? 1 : 2;
            int msk = wlast ? 1 : 3;
            int lim = 16 >> (hdec + (wlast ? 1 : 0));
            const float* bp = xi + wi * 56 + wj * 2;

            // ---- this lane's 5 gate angles (slots slot0..slot0+4, 0 if invalid)
            float gc[5], gs[5];
#pragma unroll
            for (int k = 0; k < 5; k++) {
                int slot = slot0 + k;
                int off = (slot >> sh) * 28 + (slot & msk);
                float v = (slot < lim) ? __ldg(bp + off) : 0.f;
                __sincosf(0.5f * v, &gs[k], &gc[k]);
            }

            // ---- build this lane's wire unitary ----
            float px = Ab, py = 0.f, qx = Bb, qy = 0.f;
            RZ_G(gc[0], gs[0]);
            RY_G(gc[1], gs[1]);
            RZ_G(gc[2], gs[2]);
            RY_G(gc[3], gs[3]);
            RZ_G(gc[4], gs[4]);

            // ---- share all four wires' (p,q) within the quad ----
            float p0x = __shfl_sync(0xffffffffu, px, 0, 4);
            float p0y = __shfl_sync(0xffffffffu, py, 0, 4);
            float q0x = __shfl_sync(0xffffffffu, qx, 0, 4);
            float q0y = __shfl_sync(0xffffffffu, qy, 0, 4);
            float p1x = __shfl_sync(0xffffffffu, px, 1, 4);
            float p1y = __shfl_sync(0xffffffffu, py, 1, 4);
            float q1x = __shfl_sync(0xffffffffu, qx, 1, 4);
            float q1y = __shfl_sync(0xffffffffu, qy, 1, 4);
            float p2x = __shfl_sync(0xffffffffu, px, 2, 4);
            float p2y = __shfl_sync(0xffffffffu, py, 2, 4);
            float q2x = __shfl_sync(0xffffffffu, qx, 2, 4);
            float q2y = __shfl_sync(0xffffffffu, qy, 2, 4);
            float p3x = __shfl_sync(0xffffffffu, px, 3, 4);
            float p3y = __shfl_sync(0xffffffffu, py, 3, 4);
            float q3x = __shfl_sync(0xffffffffu, qx, 3, 4);
            float q3y = __shfl_sync(0xffffffffu, qy, 3, 4);

            // ---- wire 0 (bit3, xor2) using CARRIED partner state ----
            {
                u64 Ax = bc2(side0 ? -p0x : p0x);
                u64 Bx = bc2(-p0y);
                u64 Cx = bc2(q0x);
                u64 Dx = bc2(side0 ? q0y : -q0y);
                u64 nBx = neg2(Bx), nDx = neg2(Dx);
                u64 tX0 = fma2(Ax, X0, fma2(Bx, Y0, fma2(Cx, X0c, mul2(Dx, Y0c))));
                u64 tY0 = fma2(Ax, Y0, fma2(nBx, X0, fma2(Cx, Y0c, mul2(nDx, X0c))));
                u64 tX1 = fma2(Ax, X1, fma2(Bx, Y1, fma2(Cx, X1c, mul2(Dx, Y1c))));
                u64 tY1 = fma2(Ax, Y1, fma2(nBx, X1, fma2(Cx, Y1c, mul2(nDx, X1c))));
                X0 = tX0; Y0 = tY0; X1 = tX1; Y1 = tY1;
            }
            // ---- wire 1 (bit2, xor1) ----
            {
                u64 Ax = bc2(side1 ? -p1x : p1x);
                u64 Bx = bc2(-p1y);
                u64 Cx = bc2(q1x);
                u64 Dx = bc2(side1 ? q1y : -q1y);
                u64 nBx = neg2(Bx), nDx = neg2(Dx);
                u64 X0p = shflx64(X0, 1), Y0p = shflx64(Y0, 1);
                u64 X1p = shflx64(X1, 1), Y1p = shflx64(Y1, 1);
                u64 tX0 = fma2(Ax, X0, fma2(Bx, Y0, fma2(Cx, X0p, mul2(Dx, Y0p))));
                u64 tY0 = fma2(Ax, Y0, fma2(nBx, X0, fma2(Cx, Y0p, mul2(nDx, X0p))));
                u64 tX1 = fma2(Ax, X1, fma2(Bx, Y1, fma2(Cx, X1p, mul2(Dx, Y1p))));
                u64 tY1 = fma2(Ax, Y1, fma2(nBx, X1, fma2(Cx, Y1p, mul2(nDx, X1p))));
                X0 = tX0; Y0 = tY0; X1 = tX1; Y1 = tY1;
            }
            // ---- wire 2 (bit1, local) ----
            {
                u64 PX = bc2(p2x), PY = bc2(p2y), QX = bc2(q2x), QY = bc2(q2y);
                u64 PXn = neg2(PX), PYn = neg2(PY), QYn = neg2(QY);
                u64 tX0 = fma2(PX, X0, fma2(PYn, Y0, fma2(QX, X1, mul2(QYn, Y1))));
                u64 tY0 = fma2(PX, Y0, fma2(PY, X0, fma2(QX, Y1, mul2(QY, X1))));
                u64 tX1 = fma2(QX, X0, fma2(QY, Y0, fma2(PXn, X1, mul2(PYn, Y1))));
                u64 tY1 = fma2(QX, Y0, fma2(QYn, X0, fma2(PXn, Y1, mul2(PY, X1))));
                X0 = tX0; Y0 = tY0; X1 = tX1; Y1 = tY1;
            }
            // ---- wire 3 (bit0, intra-register) ----
            {
                u64 A1 = pk2(p3x, q3x);
                u64 A2c = pk2(-p3y, q3y);
                u64 A3 = pk2(q3x, -p3x);
                u64 A4 = pk2(-q3y, -p3y);
                u64 B2c = pk2(p3y, -q3y);
                u64 B4c = pk2(q3y, p3y);
                {
                    float xa, xb, ya, yb;
                    unpk2(X0, xa, xb);
                    unpk2(Y0, ya, yb);
                    u64 bxa = bc2(xa), bxb = bc2(xb), bya = bc2(ya), byb = bc2(yb);
                    X0 = fma2(bxa, A1, fma2(bya, A2c, fma2(bxb, A3, mul2(byb, A4))));
                    Y0 = fma2(bya, A1, fma2(bxa, B2c, fma2(byb, A3, mul2(bxb, B4c))));
                }
                {
                    float xa, xb, ya, yb;
                    unpk2(X1, xa, xb);
                    unpk2(Y1, ya, yb);
                    u64 bxa = bc2(xa), bxb = bc2(xb), bya = bc2(ya), byb = bc2(yb);
                    X1 = fma2(bxa, A1, fma2(bya, A2c, fma2(bxb, A3, mul2(byb, A4))));
                    Y1 = fma2(bya, A1, fma2(bxa, B2c, fma2(byb, A3, mul2(bxb, B4c))));
                }
            }
            // ---- CRZ diagonal ----
            {
                u64 oX = X0, oY = Y0;
                X0 = fma2(PHX0, oX, neg2(mul2(PHY0, oY)));
                Y0 = fma2(PHX0, oY, mul2(PHY0, oX));
                oX = X1; oY = Y1;
                X1 = fma2(PHX1, oX, neg2(mul2(PHY1, oY)));
                Y1 = fma2(PHX1, oY, mul2(PHY1, oX));
            }

            // ---- refresh carried xor2 partner (serves x0p AND next wire0) ----
            X0c = shflx64(X0, 2); Y0c = shflx64(Y0, 2);
            X1c = shflx64(X1, 2); Y1c = shflx64(Y1, 2);

            // ---- measurement partials (rotated operator) ----
            u64 PR0 = fma2(Y0, Y0, mul2(X0, X0));
            u64 PR1 = fma2(Y1, Y1, mul2(X1, X1));
            float lo, hi;
            u64 tsum = add2(PR0, PR1);
            unpk2(tsum, lo, hi);
            float sum_pr = lo + hi;
            float d0p = sgn0 * sum_pr;
            float d1p = sgn1 * sum_pr;
            u64 tdif = sub2(PR0, PR1);
            unpk2(tdif, lo, hi);
            float d2p = lo + hi;
            unpk2(PR0, lo, hi);
            float d3p = lo - hi;
            unpk2(PR1, lo, hi);
            d3p += lo - hi;

            // local cross terms (wires 2,3)
            u64 xw2 = fma2(Y0, Y1, mul2(X0, X1));
            unpk2(xw2, lo, hi);
            float x2p = lo + hi;
            float x0a, x0b, y0a, y0b, x1a, x1b, y1a, y1b;
            unpk2(X0, x0a, x0b);
            unpk2(Y0, y0a, y0b);
            unpk2(X1, x1a, x1b);
            unpk2(Y1, y1a, y1b);
            float x3p = x0a * x0b + y0a * y0b + x1a * x1b + y1a * y1b;

            // cross-lane terms: wire0 via carried regs (free), wire1 via xor1
            u64 cx = fma2(Y0, Y0c, mul2(X0, X0c));
            cx = fma2(Y1, Y1c, fma2(X1, X1c, cx));
            unpk2(cx, lo, hi);
            float x0p = lo + hi;
            u64 X0q = shflx64(X0, 1), Y0q = shflx64(Y0, 1);
            u64 X1q = shflx64(X1, 1), Y1q = shflx64(Y1, 1);
            cx = fma2(Y0, Y0q, mul2(X0, X0q));
            cx = fma2(Y1, Y1q, fma2(X1, X1q, cx));
            unpk2(cx, lo, hi);
            float x1p = lo + hi;

            float f0p = mc * d0p - ms2h * x0p;
            float f1p = mc * d1p - ms2h * x1p;
            float f2p = mc * d2p - ms2 * x2p;
            float f3p = mc * d3p - ms2 * x3p;

            // ---- reduce features across the quad ----
            u64 fA = pk2(f0p, f1p), fB = pk2(f2p, f3p);
            fA = add2(fA, shflx64(fA, 1));
            fA = add2(fA, shflx64(fA, 2));
            fB = add2(fB, shflx64(fB, 1));
            fB = add2(fB, shflx64(fB, 2));
            float f0, f1, f2, f3;
            unpk2(fA, f0, f1);
            unpk2(fB, f2, f3);

            // ---- fc1 accumulation from transposed weights ----
            const float4* wt = g_w4t + widx * 20 + r;
#pragma unroll
            for (int t = 0; t < 5; t++) {
                float4 wv = __ldg(&wt[4 * t]);
                acc[t] += f0 * wv.x + f1 * wv.y + f2 * wv.z + f3 * wv.w;
            }

            Ab = a1;
            Bb = b1;
            widx++;
        }
    }

    // ---- fc1 bias + leaky relu + fc2 partials over owned rows ----
    float o0 = 0.f, o1 = 0.f;
#pragma unroll
    for (int t = 0; t < 5; t++) {
        int jj = 4 * t + r;
        float v = acc[t] + __ldg(fc1b + jj);
        v = v > 0.f ? v : 0.1f * v;
        o0 += v * __ldg(fc2w + jj);
        o1 += v * __ldg(fc2w + 20 + jj);
    }
    u64 po = pk2(o0, o1);
    po = add2(po, shflx64(po, 1));
    po = add2(po, shflx64(po, 2));
    if (r == 0 && img_raw < B) {
        float a, b;
        unpk2(po, a, b);
        reinterpret_cast<float2*>(out)[img] =
            make_float2(a + __ldg(fc2b + 0), b + __ldg(fc2b + 1));
    }
}

extern "C" void kernel_launch(void* const* d_in, const int* in_sizes, int n_in,
                              void* d_out, int out_size) {
    const float* x = (const float*)d_in[0];
    const float* crz_t = (const float*)d_in[1];
    const float* ry_t = (const float*)d_in[2];
    const float* fc1w = (const float*)d_in[3];
    const float* fc1b = (const float*)d_in[4];
    const float* fc2w = (const float*)d_in[5];
    const float* fc2b = (const float*)d_in[6];
    float* out = (float*)d_out;

    int B = in_sizes[0] / 784;
    transpose_fc1<<<(196 * 20 + 255) / 256, 256>>>(fc1w);
    int grid = (B + 31) / 32;   // 32 images per 128-thread block, 4 lanes/image
    multi_encoding_kernel<<<grid, 128>>>(x, crz_t, ry_t, fc1b, fc2w, fc2b, out,
                                         B);
}